// round 16
// baseline (speedup 1.0000x reference)
#include <cuda_runtime.h>
#include <cuda_fp16.h>
#include <cstdint>

// Shapes: Q[2,2048,1024], mask[2,2048], W_*[1024,1024], b_*[1024], out[2,2048,1024] fp32
// Scratch (fp16): g_qh (pre-scaled by 0.125), g_kh [bh][s][64];
//                 g_vTh [bh][64(dv)][2048(s)]; g_Ah = fp16 Q-input, g_Wh = fp16 weights
__device__ __align__(16) __half g_qh [2 * 16 * 2048 * 64];
__device__ __align__(16) __half g_kh [2 * 16 * 2048 * 64];
__device__ __align__(16) __half g_vTh[2 * 16 * 64 * 2048];
__device__ __align__(16) __half g_Ah [4096 * 1024];
__device__ __align__(16) __half g_Wh [3][1024 * 1024];

// ---------------------------------------------------------------------------
// helpers
// ---------------------------------------------------------------------------
__device__ __forceinline__ uint32_t packh(float lo, float hi) {
    uint32_t d;
    asm("cvt.rn.f16x2.f32 %0, %1, %2;" : "=r"(d) : "f"(hi), "f"(lo));
    return d;
}
__device__ __forceinline__ uint32_t smem_u32(const void* p) {
    uint32_t a;
    asm("{ .reg .u64 t; cvta.to.shared.u64 t, %1; cvt.u32.u64 %0, t; }" : "=r"(a) : "l"(p));
    return a;
}
__device__ __forceinline__ void ldsm4(uint32_t* r, uint32_t addr) {
    asm volatile("ldmatrix.sync.aligned.m8n8.x4.shared.b16 {%0,%1,%2,%3}, [%4];"
                 : "=r"(r[0]), "=r"(r[1]), "=r"(r[2]), "=r"(r[3]) : "r"(addr));
}
__device__ __forceinline__ void mma16(float* c, const uint32_t* a, const uint32_t* b) {
    asm volatile(
        "mma.sync.aligned.m16n8k16.row.col.f32.f16.f16.f32 "
        "{%0,%1,%2,%3}, {%4,%5,%6,%7}, {%8,%9}, {%0,%1,%2,%3};"
        : "+f"(c[0]), "+f"(c[1]), "+f"(c[2]), "+f"(c[3])
        : "r"(a[0]), "r"(a[1]), "r"(a[2]), "r"(a[3]), "r"(b[0]), "r"(b[1]));
}
__device__ __forceinline__ void cpa16(uint32_t dst, const void* src) {
    asm volatile("cp.async.cg.shared.global [%0], [%1], 16;" :: "r"(dst), "l"(src));
}
#define CP_COMMIT() asm volatile("cp.async.commit_group;" ::: "memory")
#define CP_WAIT1()  asm volatile("cp.async.wait_group 1;" ::: "memory")
#define CP_WAIT2()  asm volatile("cp.async.wait_group 2;" ::: "memory")

// FMA-pipe exp: exp(x) = 2^rint(u) * 2^(u-rint(u)), u = x*log2e.
// Magic-add rounding (no F2I/I2F); degree-6 Taylor for 2^f on [-0.5,0.5]
// (max rel err ~1.2e-7, tighter than MUFU EX2). Valid for |u| < 2^21.
__device__ __forceinline__ float fexp(float x) {
    const float u = x * 1.4426950408889634f;
    const float t = u + 12582912.0f;            // 2^23 + 2^22
    const float r = t - 12582912.0f;            // rint(u)
    const float f = u - r;                      // [-0.5, 0.5]
    const int  sc = (__float_as_int(t) + (127 - 4194304)) << 23;   // 2^rint(u)
    float p = 0.00015403530f;
    p = fmaf(p, f, 0.00133335581f);
    p = fmaf(p, f, 0.00961812911f);
    p = fmaf(p, f, 0.05550410866f);
    p = fmaf(p, f, 0.24022650696f);
    p = fmaf(p, f, 0.69314718056f);
    p = fmaf(p, f, 1.0f);
    return __int_as_float(sc) * p;
}

// A-operand ldmatrix byte address (16-row x k16 tile)
__device__ __forceinline__ uint32_t a_addr_h(const __half* base, int rowBase, int stride, int lane) {
    const int row = rowBase + ((lane >> 3) & 1) * 8 + (lane & 7);
    const int col = (lane >> 4) << 3;
    return smem_u32(base + row * stride + col);
}
// B-pair ldmatrix byte address -> {r0,r1}=n-group0, {r2,r3}=n-group1
__device__ __forceinline__ uint32_t b_addr_h(const __half* base, int rowBase, int stride, int lane) {
    const int sel = lane >> 3;
    const int row = rowBase + (sel >> 1) * 8 + (lane & 7);
    const int col = (sel & 1) << 3;
    return smem_u32(base + row * stride + col);
}

// ---------------------------------------------------------------------------
// fp16 pre-convert
// ---------------------------------------------------------------------------
__global__ __launch_bounds__(256)
void round_kernel(const float* __restrict__ Qin,
                  const float* __restrict__ Wq,
                  const float* __restrict__ Wk,
                  const float* __restrict__ Wv)
{
    const int i = blockIdx.x * 256 + threadIdx.x;
    const int y = blockIdx.y;
    const float* src;
    __half* dst;
    if (y == 0) { src = Qin; dst = g_Ah; }
    else        { if (i >= 262144) return;
                  src = (y == 1) ? Wq : (y == 2) ? Wk : Wv; dst = g_Wh[y - 1]; }
    const float4 v = ((const float4*)src)[i];
    ((uint2*)dst)[i] = make_uint2(packh(v.x, v.y), packh(v.z, v.w));
}

// ---------------------------------------------------------------------------
// Projection GEMM (fp16 mma) — R15 verbatim: tile M=128 N=128, K-chunk 64,
// 3-stage cp.async ring, ONE barrier per iteration. Dynamic smem.
// ---------------------------------------------------------------------------
#define PSTR 72
#define PSTG_B (256 * PSTR * 2)
#define PROJ_SMEM_BYTES (3 * PSTG_B)

__global__ __launch_bounds__(256, 2)
void proj_kernel(const float* __restrict__ bq,
                 const float* __restrict__ bk,
                 const float* __restrict__ bv)
{
    extern __shared__ __align__(16) __half psm[];
    __shared__ float s_bias[128];

    const int proj = blockIdx.z;
    const __half* A = g_Ah;
    const __half* W = g_Wh[proj];
    const float* bias = (proj == 0) ? bq : (proj == 1) ? bk : bv;

    const int tid  = threadIdx.x;
    const int lane = tid & 31;
    const int w    = tid >> 5;
    const int g    = lane >> 2;
    const int cq   = lane & 3;
    const int mw   = (w & 3) << 5;
    const int nw   = (w >> 2) << 6;
    const int m0   = blockIdx.y << 7;
    const int n0   = blockIdx.x << 7;

    if (tid < 128) s_bias[tid] = bias[n0 + tid];

    const uint32_t uS = smem_u32(psm);

    const uint32_t aAdr0 = a_addr_h(psm, mw,      PSTR, lane);
    const uint32_t aAdr1 = a_addr_h(psm, mw + 16, PSTR, lane);
    uint32_t bAdr[4];
    #pragma unroll
    for (int j = 0; j < 4; j++)
        bAdr[j] = b_addr_h(psm + 128 * PSTR, nw + 16 * j, PSTR, lane);

    const __half* srcbase = (tid < 128) ? (A + (size_t)(m0 + tid) * 1024)
                                        : (W + (size_t)(n0 + tid - 128) * 1024);
    const uint32_t drow = uS + (uint32_t)(tid * PSTR) * 2;

    float acc[2][8][4] = {};

    #pragma unroll
    for (int st = 0; st < 2; st++) {
        const int k0 = st << 6;
        #pragma unroll
        for (int i = 0; i < 8; i++)
            cpa16(drow + st * PSTG_B + i * 16, srcbase + k0 + i * 8);
        CP_COMMIT();
    }

    int cur = 0;
    for (int c = 0; c < 16; ++c) {
        const uint32_t stoff = (uint32_t)cur * PSTG_B;
        CP_WAIT1();
        __syncthreads();

        #pragma unroll
        for (int ks = 0; ks < 4; ++ks) {
            const uint32_t koff = stoff + (uint32_t)(ks << 5);
            uint32_t a0[4], a1[4];
            ldsm4(a0, aAdr0 + koff);
            ldsm4(a1, aAdr1 + koff);
            #pragma unroll
            for (int j = 0; j < 4; j++) {
                uint32_t bb[4];
                ldsm4(bb, bAdr[j] + koff);
                mma16(acc[0][2 * j],     a0, bb);
                mma16(acc[0][2 * j + 1], a0, bb + 2);
                mma16(acc[1][2 * j],     a1, bb);
                mma16(acc[1][2 * j + 1], a1, bb + 2);
            }
        }

        if (c + 2 < 16) {
            int rf = cur + 2; if (rf >= 3) rf -= 3;
            const uint32_t rfoff = (uint32_t)rf * PSTG_B;
            const int k0 = (c + 2) << 6;
            #pragma unroll
            for (int i = 0; i < 8; i++)
                cpa16(drow + rfoff + i * 16, srcbase + k0 + i * 8);
        }
        CP_COMMIT();
        cur = (cur + 1 == 3) ? 0 : cur + 1;
    }

    const int h = (n0 + nw) >> 6;
    const float qscale = (proj == 0) ? 0.125f : 1.0f;
    #pragma unroll
    for (int mt = 0; mt < 2; mt++) {
        const int m  = m0 + mw + (mt << 4) + g;
        const int b_ = m >> 11;
        const int s  = m & 2047;
        const int bh = b_ * 16 + h;
        #pragma unroll
        for (int nt = 0; nt < 8; nt++) {
            const int col  = nw + (nt << 3) + (cq << 1);
            const int colh = col & 63;
            const float b0 = s_bias[col], b1 = s_bias[col + 1];
            if (proj < 2) {
                __half* dst = (proj == 0) ? g_qh : g_kh;
                *(uint32_t*)&dst[(size_t)(bh * 2048 + s) * 64 + colh] =
                    packh((acc[mt][nt][0] + b0) * qscale, (acc[mt][nt][1] + b1) * qscale);
                *(uint32_t*)&dst[(size_t)(bh * 2048 + s + 8) * 64 + colh] =
                    packh((acc[mt][nt][2] + b0) * qscale, (acc[mt][nt][3] + b1) * qscale);
            } else {
                g_vTh[(size_t)(bh * 64 + colh)     * 2048 + s]     = __float2half_rn(acc[mt][nt][0] + b0);
                g_vTh[(size_t)(bh * 64 + colh + 1) * 2048 + s]     = __float2half_rn(acc[mt][nt][1] + b1);
                g_vTh[(size_t)(bh * 64 + colh)     * 2048 + s + 8] = __float2half_rn(acc[mt][nt][2] + b0);
                g_vTh[(size_t)(bh * 64 + colh + 1) * 2048 + s + 8] = __float2half_rn(acc[mt][nt][3] + b1);
            }
        }
    }
}

// ---------------------------------------------------------------------------
// Attention v13 (fp16): R15 structure (256 thr, warp = 16q x 64 keys, 4-stage
// ring, wait_group 2, one barrier/kt) with exp moved to the FMA pipe (fexp).
// ---------------------------------------------------------------------------
#define HSTR 72
#define KSTG_B (64 * HSTR * 2)
#define ATTN_SMEM_BYTES (128 * HSTR * 2 + 8 * KSTG_B + 4 * 64 * 4)

__global__ __launch_bounds__(256, 2)
void attn_kernel(const float* __restrict__ mask, float* __restrict__ out)
{
    extern __shared__ __align__(16) __half smh[];
    __half* Qs = smh;                        // [128 q][72]
    __half* Ks = smh + 128 * HSTR;           // [4][64 key][72]
    __half* Vs = Ks + 4 * 64 * HSTR;         // [4][64 dv][72]
    float* maskS = (float*)(Vs + 4 * 64 * HSTR);   // [4][64]

    const int tid  = threadIdx.x;
    const int lane = tid & 31;
    const int w    = tid >> 5;
    const int g    = lane >> 2;
    const int cq   = lane & 3;
    const int qw   = w << 4;
    const int q0   = blockIdx.x << 7;
    const int bh   = blockIdx.y;
    const int b    = bh >> 4;
    const int h    = bh & 15;

    const uint32_t uQ = smem_u32(Qs);
    const uint32_t uK = smem_u32(Ks);
    const uint32_t uV = smem_u32(Vs);
    const uint32_t uM = smem_u32(maskS);

    uint32_t kAdr[4], vAdr[4];
    #pragma unroll
    for (int j = 0; j < 4; j++) {
        kAdr[j] = b_addr_h(Ks, 16 * j, HSTR, lane);
        vAdr[j] = b_addr_h(Vs, 16 * j, HSTR, lane);
    }

    const int qrow = tid >> 1;
    const int qB   = (tid & 1) * 64;
    const int kvrow = tid >> 2;
    const int kvB   = (tid & 3) * 32;

    // ---- prologue: Q + tiles 0,1,2 -> stages 0,1,2 ----
    #pragma unroll
    for (int i = 0; i < 4; i++)
        cpa16(uQ + (uint32_t)(qrow * HSTR) * 2 + qB + i * 16,
              g_qh + (size_t)(bh * 2048 + q0 + qrow) * 64 + (qB >> 1) + i * 8);
    #pragma unroll
    for (int st = 0; st < 3; st++) {
        const int kb = st << 6;
        #pragma unroll
        for (int i = 0; i < 2; i++) {
            cpa16(uK + st * KSTG_B + (uint32_t)(kvrow * HSTR) * 2 + kvB + i * 16,
                  g_kh + (size_t)(bh * 2048 + kb + kvrow) * 64 + (kvB >> 1) + i * 8);
            cpa16(uV + st * KSTG_B + (uint32_t)(kvrow * HSTR) * 2 + kvB + i * 16,
                  g_vTh + (size_t)(bh * 64 + kvrow) * 2048 + kb + (kvB >> 1) + i * 8);
        }
        if (tid < 16) cpa16(uM + st * 256 + tid * 16, mask + b * 2048 + kb + tid * 4);
        CP_COMMIT();
    }
    CP_WAIT2();
    __syncthreads();

    // ---- Q fragments: load once, keep in regs ----
    uint32_t qa[4][4];
    {
        const uint32_t qb = a_addr_h(Qs, qw, HSTR, lane);
        #pragma unroll
        for (int ks = 0; ks < 4; ks++)
            ldsm4(qa[ks], qb + (ks << 5));
    }

    float acc[8][4] = {};
    float rs[2] = {};

    int cur = 0;
    for (int kt = 0; kt < 32; kt++) {
        const uint32_t stoff = (uint32_t)cur * KSTG_B;
        CP_WAIT2();
        __syncthreads();

        // ---- S = Q K^T ----
        float s[8][4] = {};
        #pragma unroll
        for (int ks = 0; ks < 4; ks++) {
            const uint32_t koff = stoff + (uint32_t)(ks << 5);
            #pragma unroll
            for (int j = 0; j < 4; j++) {
                uint32_t bb[4];
                ldsm4(bb, kAdr[j] + koff);
                mma16(s[2 * j],     qa[ks], bb);
                mma16(s[2 * j + 1], qa[ks], bb + 2);
            }
        }

        // ---- P = fexp(S)*mask (FMA-pipe exp); unrounded row sums ----
        #pragma unroll
        for (int nt = 0; nt < 8; nt++) {
            const float2 mm = *(const float2*)&maskS[cur * 64 + (nt << 3) + (cq << 1)];
            const float p00 = fexp(s[nt][0]) * mm.x;
            const float p01 = fexp(s[nt][1]) * mm.y;
            const float p10 = fexp(s[nt][2]) * mm.x;
            const float p11 = fexp(s[nt][3]) * mm.y;
            rs[0] += p00 + p01;
            rs[1] += p10 + p11;
            s[nt][0] = p00; s[nt][1] = p01; s[nt][2] = p10; s[nt][3] = p11;
        }

        // ---- acc += P @ V ----
        #pragma unroll
        for (int t = 0; t < 4; t++) {
            const uint32_t koff = stoff + (uint32_t)(t << 5);
            uint32_t a[4] = { packh(s[2*t][0],   s[2*t][1]),   packh(s[2*t][2],   s[2*t][3]),
                              packh(s[2*t+1][0], s[2*t+1][1]), packh(s[2*t+1][2], s[2*t+1][3]) };
            #pragma unroll
            for (int j = 0; j < 4; j++) {
                uint32_t bb[4];
                ldsm4(bb, vAdr[j] + koff);
                mma16(acc[2 * j],     a, bb);
                mma16(acc[2 * j + 1], a, bb + 2);
            }
        }

        // ---- refill stage (cur+3)%4 with tile kt+3 ----
        if (kt + 3 < 32) {
            int rf = cur + 3; if (rf >= 4) rf -= 4;
            const uint32_t rfoff = (uint32_t)rf * KSTG_B;
            const int kn = (kt + 3) << 6;
            #pragma unroll
            for (int i = 0; i < 2; i++) {
                cpa16(uK + rfoff + (uint32_t)(kvrow * HSTR) * 2 + kvB + i * 16,
                      g_kh + (size_t)(bh * 2048 + kn + kvrow) * 64 + (kvB >> 1) + i * 8);
                cpa16(uV + rfoff + (uint32_t)(kvrow * HSTR) * 2 + kvB + i * 16,
                      g_vTh + (size_t)(bh * 64 + kvrow) * 2048 + kn + (kvB >> 1) + i * 8);
            }
            if (tid < 16) cpa16(uM + rf * 256 + tid * 16, mask + b * 2048 + kn + tid * 4);
        }
        CP_COMMIT();
        cur = (cur + 1 == 4) ? 0 : cur + 1;
    }

    // ---- denominator: reduce across the 4 cq lanes ----
    #pragma unroll
    for (int i = 0; i < 2; i++) {
        rs[i] += __shfl_xor_sync(0xffffffffu, rs[i], 1);
        rs[i] += __shfl_xor_sync(0xffffffffu, rs[i], 2);
        rs[i] = 1.0f / (rs[i] + 1e-8f);
    }

    const int q_lo = q0 + qw + g;
    #pragma unroll
    for (int nt = 0; nt < 8; nt++) {
        const int dv = (nt << 3) + (cq << 1);
        *(float2*)&out[(size_t)((b * 2048 + q_lo) * 16 + h) * 64 + dv] =
            make_float2(acc[nt][0] * rs[0], acc[nt][1] * rs[0]);
        *(float2*)&out[(size_t)((b * 2048 + q_lo + 8) * 16 + h) * 64 + dv] =
            make_float2(acc[nt][2] * rs[1], acc[nt][3] * rs[1]);
    }
}

// ---------------------------------------------------------------------------
extern "C" void kernel_launch(void* const* d_in, const int* in_sizes, int n_in,
                              void* d_out, int out_size)
{
    const float* Q    = (const float*)d_in[0];
    const float* mask = (const float*)d_in[1];
    const float* Wq   = (const float*)d_in[2];
    const float* bq   = (const float*)d_in[3];
    const float* Wk   = (const float*)d_in[4];
    const float* bk   = (const float*)d_in[5];
    const float* Wv   = (const float*)d_in[6];
    const float* bv   = (const float*)d_in[7];
    float* out = (float*)d_out;

    cudaFuncSetAttribute(proj_kernel,
                         cudaFuncAttributeMaxDynamicSharedMemorySize, PROJ_SMEM_BYTES);
    cudaFuncSetAttribute(attn_kernel,
                         cudaFuncAttributeMaxDynamicSharedMemorySize, ATTN_SMEM_BYTES);

    round_kernel<<<dim3(4096, 4), 256>>>(Q, Wq, Wk, Wv);
    proj_kernel<<<dim3(8, 32, 3), 256, PROJ_SMEM_BYTES>>>(bq, bk, bv);
    attn_kernel<<<dim3(16, 32), 256, ATTN_SMEM_BYTES>>>(mask, out);
}

// round 17
// speedup vs baseline: 1.1127x; 1.1127x over previous
#include <cuda_runtime.h>
#include <cuda_fp16.h>
#include <cstdint>

// Shapes: Q[2,2048,1024], mask[2,2048], W_*[1024,1024], b_*[1024], out[2,2048,1024] fp32
// Scratch (fp16): g_qh (pre-scaled by 0.125), g_kh [bh][s][64];
//                 g_vTh [bh][64(dv)][2048(s)]; g_Ah = fp16 Q-input, g_Wh = fp16 weights
__device__ __align__(16) __half g_qh [2 * 16 * 2048 * 64];
__device__ __align__(16) __half g_kh [2 * 16 * 2048 * 64];
__device__ __align__(16) __half g_vTh[2 * 16 * 64 * 2048];
__device__ __align__(16) __half g_Ah [4096 * 1024];
__device__ __align__(16) __half g_Wh [3][1024 * 1024];

// ---------------------------------------------------------------------------
// helpers
// ---------------------------------------------------------------------------
__device__ __forceinline__ uint32_t packh(float lo, float hi) {
    uint32_t d;
    asm("cvt.rn.f16x2.f32 %0, %1, %2;" : "=r"(d) : "f"(hi), "f"(lo));
    return d;
}
__device__ __forceinline__ uint32_t smem_u32(const void* p) {
    uint32_t a;
    asm("{ .reg .u64 t; cvta.to.shared.u64 t, %1; cvt.u32.u64 %0, t; }" : "=r"(a) : "l"(p));
    return a;
}
__device__ __forceinline__ void ldsm4(uint32_t* r, uint32_t addr) {
    asm volatile("ldmatrix.sync.aligned.m8n8.x4.shared.b16 {%0,%1,%2,%3}, [%4];"
                 : "=r"(r[0]), "=r"(r[1]), "=r"(r[2]), "=r"(r[3]) : "r"(addr));
}
__device__ __forceinline__ void mma16(float* c, const uint32_t* a, const uint32_t* b) {
    asm volatile(
        "mma.sync.aligned.m16n8k16.row.col.f32.f16.f16.f32 "
        "{%0,%1,%2,%3}, {%4,%5,%6,%7}, {%8,%9}, {%0,%1,%2,%3};"
        : "+f"(c[0]), "+f"(c[1]), "+f"(c[2]), "+f"(c[3])
        : "r"(a[0]), "r"(a[1]), "r"(a[2]), "r"(a[3]), "r"(b[0]), "r"(b[1]));
}
__device__ __forceinline__ void cpa16(uint32_t dst, const void* src) {
    asm volatile("cp.async.cg.shared.global [%0], [%1], 16;" :: "r"(dst), "l"(src));
}
#define CP_COMMIT() asm volatile("cp.async.commit_group;" ::: "memory")
#define CP_WAIT1()  asm volatile("cp.async.wait_group 1;" ::: "memory")
#define CP_WAIT2()  asm volatile("cp.async.wait_group 2;" ::: "memory")

// A-operand ldmatrix byte address (16-row x k16 tile)
__device__ __forceinline__ uint32_t a_addr_h(const __half* base, int rowBase, int stride, int lane) {
    const int row = rowBase + ((lane >> 3) & 1) * 8 + (lane & 7);
    const int col = (lane >> 4) << 3;
    return smem_u32(base + row * stride + col);
}
// B-pair ldmatrix byte address -> {r0,r1}=n-group0, {r2,r3}=n-group1
__device__ __forceinline__ uint32_t b_addr_h(const __half* base, int rowBase, int stride, int lane) {
    const int sel = lane >> 3;
    const int row = rowBase + (sel >> 1) * 8 + (lane & 7);
    const int col = (sel & 1) << 3;
    return smem_u32(base + row * stride + col);
}

// ---------------------------------------------------------------------------
// fp16 pre-convert
// ---------------------------------------------------------------------------
__global__ __launch_bounds__(256)
void round_kernel(const float* __restrict__ Qin,
                  const float* __restrict__ Wq,
                  const float* __restrict__ Wk,
                  const float* __restrict__ Wv)
{
    const int i = blockIdx.x * 256 + threadIdx.x;
    const int y = blockIdx.y;
    const float* src;
    __half* dst;
    if (y == 0) { src = Qin; dst = g_Ah; }
    else        { if (i >= 262144) return;
                  src = (y == 1) ? Wq : (y == 2) ? Wk : Wv; dst = g_Wh[y - 1]; }
    const float4 v = ((const float4*)src)[i];
    ((uint2*)dst)[i] = make_uint2(packh(v.x, v.y), packh(v.z, v.w));
}

// ---------------------------------------------------------------------------
// Projection GEMM (fp16 mma) — R15 verbatim: tile M=128 N=128, K-chunk 64,
// 3-stage cp.async ring, ONE barrier per iteration. Dynamic smem.
// ---------------------------------------------------------------------------
#define PSTR 72
#define PSTG_B (256 * PSTR * 2)
#define PROJ_SMEM_BYTES (3 * PSTG_B)

__global__ __launch_bounds__(256, 2)
void proj_kernel(const float* __restrict__ bq,
                 const float* __restrict__ bk,
                 const float* __restrict__ bv)
{
    extern __shared__ __align__(16) __half psm[];
    __shared__ float s_bias[128];

    const int proj = blockIdx.z;
    const __half* A = g_Ah;
    const __half* W = g_Wh[proj];
    const float* bias = (proj == 0) ? bq : (proj == 1) ? bk : bv;

    const int tid  = threadIdx.x;
    const int lane = tid & 31;
    const int w    = tid >> 5;
    const int g    = lane >> 2;
    const int cq   = lane & 3;
    const int mw   = (w & 3) << 5;
    const int nw   = (w >> 2) << 6;
    const int m0   = blockIdx.y << 7;
    const int n0   = blockIdx.x << 7;

    if (tid < 128) s_bias[tid] = bias[n0 + tid];

    const uint32_t uS = smem_u32(psm);

    const uint32_t aAdr0 = a_addr_h(psm, mw,      PSTR, lane);
    const uint32_t aAdr1 = a_addr_h(psm, mw + 16, PSTR, lane);
    uint32_t bAdr[4];
    #pragma unroll
    for (int j = 0; j < 4; j++)
        bAdr[j] = b_addr_h(psm + 128 * PSTR, nw + 16 * j, PSTR, lane);

    const __half* srcbase = (tid < 128) ? (A + (size_t)(m0 + tid) * 1024)
                                        : (W + (size_t)(n0 + tid - 128) * 1024);
    const uint32_t drow = uS + (uint32_t)(tid * PSTR) * 2;

    float acc[2][8][4] = {};

    #pragma unroll
    for (int st = 0; st < 2; st++) {
        const int k0 = st << 6;
        #pragma unroll
        for (int i = 0; i < 8; i++)
            cpa16(drow + st * PSTG_B + i * 16, srcbase + k0 + i * 8);
        CP_COMMIT();
    }

    int cur = 0;
    for (int c = 0; c < 16; ++c) {
        const uint32_t stoff = (uint32_t)cur * PSTG_B;
        CP_WAIT1();
        __syncthreads();

        #pragma unroll
        for (int ks = 0; ks < 4; ++ks) {
            const uint32_t koff = stoff + (uint32_t)(ks << 5);
            uint32_t a0[4], a1[4];
            ldsm4(a0, aAdr0 + koff);
            ldsm4(a1, aAdr1 + koff);
            #pragma unroll
            for (int j = 0; j < 4; j++) {
                uint32_t bb[4];
                ldsm4(bb, bAdr[j] + koff);
                mma16(acc[0][2 * j],     a0, bb);
                mma16(acc[0][2 * j + 1], a0, bb + 2);
                mma16(acc[1][2 * j],     a1, bb);
                mma16(acc[1][2 * j + 1], a1, bb + 2);
            }
        }

        if (c + 2 < 16) {
            int rf = cur + 2; if (rf >= 3) rf -= 3;
            const uint32_t rfoff = (uint32_t)rf * PSTG_B;
            const int k0 = (c + 2) << 6;
            #pragma unroll
            for (int i = 0; i < 8; i++)
                cpa16(drow + rfoff + i * 16, srcbase + k0 + i * 8);
        }
        CP_COMMIT();
        cur = (cur + 1 == 3) ? 0 : cur + 1;
    }

    const int h = (n0 + nw) >> 6;
    const float qscale = (proj == 0) ? 0.125f : 1.0f;
    #pragma unroll
    for (int mt = 0; mt < 2; mt++) {
        const int m  = m0 + mw + (mt << 4) + g;
        const int b_ = m >> 11;
        const int s  = m & 2047;
        const int bh = b_ * 16 + h;
        #pragma unroll
        for (int nt = 0; nt < 8; nt++) {
            const int col  = nw + (nt << 3) + (cq << 1);
            const int colh = col & 63;
            const float b0 = s_bias[col], b1 = s_bias[col + 1];
            if (proj < 2) {
                __half* dst = (proj == 0) ? g_qh : g_kh;
                *(uint32_t*)&dst[(size_t)(bh * 2048 + s) * 64 + colh] =
                    packh((acc[mt][nt][0] + b0) * qscale, (acc[mt][nt][1] + b1) * qscale);
                *(uint32_t*)&dst[(size_t)(bh * 2048 + s + 8) * 64 + colh] =
                    packh((acc[mt][nt][2] + b0) * qscale, (acc[mt][nt][3] + b1) * qscale);
            } else {
                g_vTh[(size_t)(bh * 64 + colh)     * 2048 + s]     = __float2half_rn(acc[mt][nt][0] + b0);
                g_vTh[(size_t)(bh * 64 + colh + 1) * 2048 + s]     = __float2half_rn(acc[mt][nt][1] + b1);
                g_vTh[(size_t)(bh * 64 + colh)     * 2048 + s + 8] = __float2half_rn(acc[mt][nt][2] + b0);
                g_vTh[(size_t)(bh * 64 + colh + 1) * 2048 + s + 8] = __float2half_rn(acc[mt][nt][3] + b1);
            }
        }
    }
}

// ---------------------------------------------------------------------------
// Attention v14 (fp16): R15 structure (256 thr, warp = 16q x 64 keys, 4-stage
// ring, wait_group 2, one barrier/kt) with a per-key-group software pipeline:
// for j: S(keys 16j..16j+15) -> exp/mask -> PV(chunk j). Same FP order as R15
// per output element -> bit-identical. Breaks S/exp/PV phase alignment.
// ---------------------------------------------------------------------------
#define HSTR 72
#define KSTG_B (64 * HSTR * 2)
#define ATTN_SMEM_BYTES (128 * HSTR * 2 + 8 * KSTG_B + 4 * 64 * 4)

__global__ __launch_bounds__(256, 2)
void attn_kernel(const float* __restrict__ mask, float* __restrict__ out)
{
    extern __shared__ __align__(16) __half smh[];
    __half* Qs = smh;                        // [128 q][72]
    __half* Ks = smh + 128 * HSTR;           // [4][64 key][72]
    __half* Vs = Ks + 4 * 64 * HSTR;         // [4][64 dv][72]
    float* maskS = (float*)(Vs + 4 * 64 * HSTR);   // [4][64]

    const int tid  = threadIdx.x;
    const int lane = tid & 31;
    const int w    = tid >> 5;
    const int g    = lane >> 2;
    const int cq   = lane & 3;
    const int qw   = w << 4;
    const int q0   = blockIdx.x << 7;
    const int bh   = blockIdx.y;
    const int b    = bh >> 4;
    const int h    = bh & 15;

    const uint32_t uQ = smem_u32(Qs);
    const uint32_t uK = smem_u32(Ks);
    const uint32_t uV = smem_u32(Vs);
    const uint32_t uM = smem_u32(maskS);

    uint32_t kAdr[4], vAdr[4];
    #pragma unroll
    for (int j = 0; j < 4; j++) {
        kAdr[j] = b_addr_h(Ks, 16 * j, HSTR, lane);
        vAdr[j] = b_addr_h(Vs, 16 * j, HSTR, lane);
    }

    const int qrow = tid >> 1;
    const int qB   = (tid & 1) * 64;
    const int kvrow = tid >> 2;
    const int kvB   = (tid & 3) * 32;

    // ---- prologue: Q + tiles 0,1,2 -> stages 0,1,2 ----
    #pragma unroll
    for (int i = 0; i < 4; i++)
        cpa16(uQ + (uint32_t)(qrow * HSTR) * 2 + qB + i * 16,
              g_qh + (size_t)(bh * 2048 + q0 + qrow) * 64 + (qB >> 1) + i * 8);
    #pragma unroll
    for (int st = 0; st < 3; st++) {
        const int kb = st << 6;
        #pragma unroll
        for (int i = 0; i < 2; i++) {
            cpa16(uK + st * KSTG_B + (uint32_t)(kvrow * HSTR) * 2 + kvB + i * 16,
                  g_kh + (size_t)(bh * 2048 + kb + kvrow) * 64 + (kvB >> 1) + i * 8);
            cpa16(uV + st * KSTG_B + (uint32_t)(kvrow * HSTR) * 2 + kvB + i * 16,
                  g_vTh + (size_t)(bh * 64 + kvrow) * 2048 + kb + (kvB >> 1) + i * 8);
        }
        if (tid < 16) cpa16(uM + st * 256 + tid * 16, mask + b * 2048 + kb + tid * 4);
        CP_COMMIT();
    }
    CP_WAIT2();
    __syncthreads();

    // ---- Q fragments: load once, keep in regs ----
    uint32_t qa[4][4];
    {
        const uint32_t qb = a_addr_h(Qs, qw, HSTR, lane);
        #pragma unroll
        for (int ks = 0; ks < 4; ks++)
            ldsm4(qa[ks], qb + (ks << 5));
    }

    float acc[8][4] = {};
    float rs[2] = {};

    int cur = 0;
    for (int kt = 0; kt < 32; kt++) {
        const uint32_t stoff = (uint32_t)cur * KSTG_B;
        CP_WAIT2();
        __syncthreads();

        // ---- per-key-group pipeline: S(j) -> exp(j) -> PV(t=j) ----
        #pragma unroll
        for (int j = 0; j < 4; j++) {
            // S for key groups 2j, 2j+1 (keys 16j..16j+15), all 4 ks steps
            float s0[4] = {}, s1[4] = {};
            #pragma unroll
            for (int ks = 0; ks < 4; ks++) {
                uint32_t bb[4];
                ldsm4(bb, kAdr[j] + stoff + (uint32_t)(ks << 5));
                mma16(s0, qa[ks], bb);
                mma16(s1, qa[ks], bb + 2);
            }

            // exp + mask + row sums (same nt order as before: 2j then 2j+1)
            const float2 mmA = *(const float2*)&maskS[cur * 64 + ((2 * j) << 3) + (cq << 1)];
            const float2 mmB = *(const float2*)&maskS[cur * 64 + ((2 * j + 1) << 3) + (cq << 1)];
            const float pA0 = __expf(s0[0]) * mmA.x;
            const float pA1 = __expf(s0[1]) * mmA.y;
            const float pA2 = __expf(s0[2]) * mmA.x;
            const float pA3 = __expf(s0[3]) * mmA.y;
            rs[0] += pA0 + pA1;
            rs[1] += pA2 + pA3;
            const float pB0 = __expf(s1[0]) * mmB.x;
            const float pB1 = __expf(s1[1]) * mmB.y;
            const float pB2 = __expf(s1[2]) * mmB.x;
            const float pB3 = __expf(s1[3]) * mmB.y;
            rs[0] += pB0 + pB1;
            rs[1] += pB2 + pB3;

            // PV for key chunk t=j: A = f16x2 packs (same layout as before)
            uint32_t a[4] = { packh(pA0, pA1), packh(pA2, pA3),
                              packh(pB0, pB1), packh(pB2, pB3) };
            const uint32_t koffV = stoff + (uint32_t)(j << 5);
            #pragma unroll
            for (int jj = 0; jj < 4; jj++) {
                uint32_t bb[4];
                ldsm4(bb, vAdr[jj] + koffV);
                mma16(acc[2 * jj],     a, bb);
                mma16(acc[2 * jj + 1], a, bb + 2);
            }
        }

        // ---- refill stage (cur+3)%4 with tile kt+3 ----
        if (kt + 3 < 32) {
            int rf = cur + 3; if (rf >= 4) rf -= 4;
            const uint32_t rfoff = (uint32_t)rf * KSTG_B;
            const int kn = (kt + 3) << 6;
            #pragma unroll
            for (int i = 0; i < 2; i++) {
                cpa16(uK + rfoff + (uint32_t)(kvrow * HSTR) * 2 + kvB + i * 16,
                      g_kh + (size_t)(bh * 2048 + kn + kvrow) * 64 + (kvB >> 1) + i * 8);
                cpa16(uV + rfoff + (uint32_t)(kvrow * HSTR) * 2 + kvB + i * 16,
                      g_vTh + (size_t)(bh * 64 + kvrow) * 2048 + kn + (kvB >> 1) + i * 8);
            }
            if (tid < 16) cpa16(uM + rf * 256 + tid * 16, mask + b * 2048 + kn + tid * 4);
        }
        CP_COMMIT();
        cur = (cur + 1 == 4) ? 0 : cur + 1;
    }

    // ---- denominator: reduce across the 4 cq lanes ----
    #pragma unroll
    for (int i = 0; i < 2; i++) {
        rs[i] += __shfl_xor_sync(0xffffffffu, rs[i], 1);
        rs[i] += __shfl_xor_sync(0xffffffffu, rs[i], 2);
        rs[i] = 1.0f / (rs[i] + 1e-8f);
    }

    const int q_lo = q0 + qw + g;
    #pragma unroll
    for (int nt = 0; nt < 8; nt++) {
        const int dv = (nt << 3) + (cq << 1);
        *(float2*)&out[(size_t)((b * 2048 + q_lo) * 16 + h) * 64 + dv] =
            make_float2(acc[nt][0] * rs[0], acc[nt][1] * rs[0]);
        *(float2*)&out[(size_t)((b * 2048 + q_lo + 8) * 16 + h) * 64 + dv] =
            make_float2(acc[nt][2] * rs[1], acc[nt][3] * rs[1]);
    }
}

// ---------------------------------------------------------------------------
extern "C" void kernel_launch(void* const* d_in, const int* in_sizes, int n_in,
                              void* d_out, int out_size)
{
    const float* Q    = (const float*)d_in[0];
    const float* mask = (const float*)d_in[1];
    const float* Wq   = (const float*)d_in[2];
    const float* bq   = (const float*)d_in[3];
    const float* Wk   = (const float*)d_in[4];
    const float* bk   = (const float*)d_in[5];
    const float* Wv   = (const float*)d_in[6];
    const float* bv   = (const float*)d_in[7];
    float* out = (float*)d_out;

    cudaFuncSetAttribute(proj_kernel,
                         cudaFuncAttributeMaxDynamicSharedMemorySize, PROJ_SMEM_BYTES);
    cudaFuncSetAttribute(attn_kernel,
                         cudaFuncAttributeMaxDynamicSharedMemorySize, ATTN_SMEM_BYTES);

    round_kernel<<<dim3(4096, 4), 256>>>(Q, Wq, Wk, Wv);
    proj_kernel<<<dim3(8, 32, 3), 256, PROJ_SMEM_BYTES>>>(bq, bk, bv);
    attn_kernel<<<dim3(16, 32), 256, ATTN_SMEM_BYTES>>>(mask, out);
}